// round 1
// baseline (speedup 1.0000x reference)
#include <cuda_runtime.h>
#include <cstdint>

// ---------------------------------------------------------------------------
// Swin WindowAttention, fused per-window kernel, TF32 mma.sync (m16n8k8).
//   x[4096,49,128] -> qkv -> 4-head attn (+rel-pos bias, +mask) -> proj
// One CTA per window, 256 threads (8 warps). Token dim padded 49 -> 64.
// ---------------------------------------------------------------------------

namespace {
constexpr int NTOK  = 49;    // tokens per window
constexpr int CDIM  = 128;   // channels
constexpr int NHEAD = 4;
constexpr int TC3   = 384;   // 3*C

// shared memory layout (float offsets). Strides chosen so fragment LDS
// patterns are bank-conflict free:
//   A-fragment pattern (addr = row(g)*S + col(tig))      needs S % 32 == 4
//   B-fragment pattern (addr = row(tig)*S + col(g))      needs S % 32 == 8
constexpr int XS_STR = 132;  // x / attn-out buffer  [64][132]   (A operand, %32==4)
constexpr int QK_STR = 260;  // q,k buffer           [64][260]   (A+B-via-row, %32==4)
constexpr int VB_STR = 136;  // v buffer             [64][136]   (B operand, %32==8)
constexpr int WS_STR = 392;  // qkv_w k-slice        [16][392]   (B operand, %32==8)
constexpr int WP_STR = 136;  // proj_w k-slice       [16][136]   (B operand, %32==8)
constexpr int LB_STR = 68;   // logits/P buffer      [64][68]    (A operand, %32==4)

constexpr int OFF_XS = 0;                        // 64*132 = 8448
constexpr int OFF_QK = OFF_XS + 64 * XS_STR;     // 8448
constexpr int OFF_VB = OFF_QK + 64 * QK_STR;     // 25088
constexpr int OFF_WS = OFF_VB + 64 * VB_STR;     // 33792
constexpr int OFF_LB = OFF_WS + 16 * WS_STR;     // 40064
constexpr int OFF_MS = OFF_LB + 64 * LB_STR;     // 44416   mask [49*49]
constexpr int OFF_BT = OFF_MS + NTOK * NTOK;     // 46817   bias table [169*4]
constexpr int SMEM_FLOATS = OFF_BT + 169 * NHEAD;// 47493 floats = 189972 B
}

// round fp32 -> tf32 (round to nearest), keep as fp32 bit pattern
__device__ __forceinline__ float tfs(float f) {
    unsigned r;
    asm("cvt.rna.tf32.f32 %0, %1;" : "=r"(r) : "f"(f));
    return __uint_as_float(r);
}

__device__ __forceinline__ void mma8(float* c,
                                     unsigned a0, unsigned a1, unsigned a2, unsigned a3,
                                     unsigned b0, unsigned b1) {
    asm volatile(
        "mma.sync.aligned.m16n8k8.row.col.f32.tf32.tf32.f32 "
        "{%0,%1,%2,%3}, {%4,%5,%6,%7}, {%8,%9}, {%0,%1,%2,%3};"
        : "+f"(c[0]), "+f"(c[1]), "+f"(c[2]), "+f"(c[3])
        : "r"(a0), "r"(a1), "r"(a2), "r"(a3), "r"(b0), "r"(b1));
}

#define F2U(x) __float_as_uint(x)

__global__ __launch_bounds__(256, 1) void win_attn_kernel(
    const float* __restrict__ x,       const float* __restrict__ qkv_w,
    const float* __restrict__ qkv_b,   const float* __restrict__ proj_w,
    const float* __restrict__ proj_b,  const float* __restrict__ bias_t,
    const float* __restrict__ mask,    float* __restrict__ out,
    int nmask)
{
    extern __shared__ float sm[];
    float* XS = sm + OFF_XS;
    float* QK = sm + OFF_QK;
    float* VB = sm + OFF_VB;
    float* WSm = sm + OFF_WS;
    float* LB = sm + OFF_LB;
    float* MS = sm + OFF_MS;
    float* BT = sm + OFF_BT;

    const int w    = blockIdx.x;
    const int tid  = threadIdx.x;
    const int warp = tid >> 5;
    const int lane = tid & 31;
    const int g    = lane >> 2;   // groupID (0..7)
    const int tig  = lane & 3;    // thread-in-group (0..3)

    // ---------------- Phase 0: load x window, mask row, bias table ---------
    {
        const float4* xg = reinterpret_cast<const float4*>(x + (size_t)w * NTOK * CDIM);
        for (int idx = tid; idx < NTOK * 32; idx += 256) {
            int r = idx >> 5, c4 = idx & 31;
            float4 v = xg[r * 32 + c4];
            float* d = XS + r * XS_STR + c4 * 4;
            d[0] = tfs(v.x); d[1] = tfs(v.y); d[2] = tfs(v.z); d[3] = tfs(v.w);
        }
        // zero padded rows 49..63 (all 132 cols)
        for (int idx = tid; idx < 15 * XS_STR; idx += 256)
            XS[NTOK * XS_STR + idx] = 0.0f;

        const float* mg = mask + (size_t)(w % nmask) * NTOK * NTOK;
        for (int idx = tid; idx < NTOK * NTOK; idx += 256) MS[idx] = mg[idx];
        for (int idx = tid; idx < 169 * NHEAD; idx += 256) BT[idx] = bias_t[idx];
    }
    __syncthreads();

    // ---------------- GEMM1: qkv[64,384] = XS[64,128] @ qkv_w + b ----------
    {
        float acc[24][4];
#pragma unroll
        for (int t = 0; t < 24; t++) { acc[t][0] = acc[t][1] = acc[t][2] = acc[t][3] = 0.f; }
        const int mt = warp & 3, ng = warp >> 2;
        const int rb = mt * 16;

        for (int kk = 0; kk < 8; kk++) {
            // stage qkv_w rows [kk*16, kk*16+16) x [0,384) -> WSm, tf32-rounded
            const float4* wg = reinterpret_cast<const float4*>(qkv_w + (size_t)kk * 16 * TC3);
            for (int idx = tid; idx < 16 * 96; idx += 256) {
                int r = idx / 96, c4 = idx % 96;
                float4 v = wg[r * 96 + c4];
                float* d = WSm + r * WS_STR + c4 * 4;
                d[0] = tfs(v.x); d[1] = tfs(v.y); d[2] = tfs(v.z); d[3] = tfs(v.w);
            }
            __syncthreads();
#pragma unroll
            for (int k2 = 0; k2 < 2; k2++) {
                const int kc = kk * 16 + k2 * 8;   // global k col in XS
                unsigned a0 = F2U(XS[(rb + g)     * XS_STR + kc + tig]);
                unsigned a1 = F2U(XS[(rb + g + 8) * XS_STR + kc + tig]);
                unsigned a2 = F2U(XS[(rb + g)     * XS_STR + kc + tig + 4]);
                unsigned a3 = F2U(XS[(rb + g + 8) * XS_STR + kc + tig + 4]);
#pragma unroll
                for (int t = 0; t < 24; t++) {
                    const int n8 = ng * 24 + t;
                    unsigned b0 = F2U(WSm[(k2 * 8 + tig)     * WS_STR + n8 * 8 + g]);
                    unsigned b1 = F2U(WSm[(k2 * 8 + tig + 4) * WS_STR + n8 * 8 + g]);
                    mma8(acc[t], a0, a1, a2, a3, b0, b1);
                }
            }
            __syncthreads();
        }
        // epilogue: +bias, scale q, split into QK / VB, tf32-rounded
        const float scale = 0.17677669529663687f;  // 32^-0.5
#pragma unroll
        for (int t = 0; t < 24; t++) {
            const int n8 = ng * 24 + t;
            const int c0 = n8 * 8 + 2 * tig, c1 = c0 + 1;
            const int r0 = rb + g, r1 = rb + g + 8;
            const float bb0 = qkv_b[c0], bb1 = qkv_b[c1];
            float v00 = acc[t][0] + bb0, v01 = acc[t][1] + bb1;
            float v10 = acc[t][2] + bb0, v11 = acc[t][3] + bb1;
            if (c0 < 128) { v00 *= scale; v01 *= scale; v10 *= scale; v11 *= scale; }
            if (c0 < 256) {
                QK[r0 * QK_STR + c0] = tfs(v00); QK[r0 * QK_STR + c1] = tfs(v01);
                QK[r1 * QK_STR + c0] = tfs(v10); QK[r1 * QK_STR + c1] = tfs(v11);
            } else {
                VB[r0 * VB_STR + c0 - 256] = tfs(v00); VB[r0 * VB_STR + c1 - 256] = tfs(v01);
                VB[r1 * VB_STR + c0 - 256] = tfs(v10); VB[r1 * VB_STR + c1 - 256] = tfs(v11);
            }
        }
    }
    __syncthreads();

    // ---------------- Attention: per head (sequential, reuse LB) -----------
    for (int h = 0; h < NHEAD; h++) {
        // GEMM2: logits[64,64] = q_h[64,32] @ k_h[64,32]^T  (q already scaled)
        {
            const int mt = warp & 3, ng = warp >> 2;
            const int rb = mt * 16;
            float acc[4][4];
#pragma unroll
            for (int t = 0; t < 4; t++) { acc[t][0] = acc[t][1] = acc[t][2] = acc[t][3] = 0.f; }
#pragma unroll
            for (int kk = 0; kk < 4; kk++) {
                const int kc = h * 32 + kk * 8;
                unsigned a0 = F2U(QK[(rb + g)     * QK_STR + kc + tig]);
                unsigned a1 = F2U(QK[(rb + g + 8) * QK_STR + kc + tig]);
                unsigned a2 = F2U(QK[(rb + g)     * QK_STR + kc + tig + 4]);
                unsigned a3 = F2U(QK[(rb + g + 8) * QK_STR + kc + tig + 4]);
#pragma unroll
                for (int t = 0; t < 4; t++) {
                    const int n8 = ng * 4 + t;
                    unsigned b0 = F2U(QK[(n8 * 8 + g) * QK_STR + 128 + kc + tig]);
                    unsigned b1 = F2U(QK[(n8 * 8 + g) * QK_STR + 128 + kc + tig + 4]);
                    mma8(acc[t], a0, a1, a2, a3, b0, b1);
                }
            }
#pragma unroll
            for (int t = 0; t < 4; t++) {
                const int n8 = ng * 4 + t;
                const int c0 = n8 * 8 + 2 * tig;
                LB[(rb + g)     * LB_STR + c0]     = acc[t][0];
                LB[(rb + g)     * LB_STR + c0 + 1] = acc[t][1];
                LB[(rb + g + 8) * LB_STR + c0]     = acc[t][2];
                LB[(rb + g + 8) * LB_STR + c0 + 1] = acc[t][3];
            }
        }
        __syncthreads();

        // softmax rows (one warp per row, 8 rows per warp); +rpb, +mask
        for (int rr = 0; rr < 8; rr++) {
            const int i = warp + rr * 8;
            if (i < NTOK) {
                const int ri = i / 7, ci = i - ri * 7;
                float v1, v2;
                {
                    const int j = lane;           // < 32 < 49, always valid
                    const int rj = j / 7, cj = j - rj * 7;
                    const int idx = (ri - rj + 6) * 13 + (ci - cj + 6);
                    v1 = LB[i * LB_STR + j] + BT[idx * NHEAD + h] + MS[i * NTOK + j];
                }
                const int j2 = lane + 32;
                if (j2 < NTOK) {
                    const int rj = j2 / 7, cj = j2 - rj * 7;
                    const int idx = (ri - rj + 6) * 13 + (ci - cj + 6);
                    v2 = LB[i * LB_STR + j2] + BT[idx * NHEAD + h] + MS[i * NTOK + j2];
                } else {
                    v2 = -3.0e38f;
                }
                float m = fmaxf(v1, v2);
#pragma unroll
                for (int o = 16; o > 0; o >>= 1) m = fmaxf(m, __shfl_xor_sync(0xffffffffu, m, o));
                float e1 = __expf(v1 - m);
                float e2 = (j2 < NTOK) ? __expf(v2 - m) : 0.f;
                float s = e1 + e2;
#pragma unroll
                for (int o = 16; o > 0; o >>= 1) s += __shfl_xor_sync(0xffffffffu, s, o);
                const float inv = 1.0f / s;
                LB[i * LB_STR + lane] = tfs(e1 * inv);
                LB[i * LB_STR + j2]   = (j2 < NTOK) ? tfs(e2 * inv) : 0.f;
            } else {
                // padded rows: P = 0
                LB[i * LB_STR + lane]      = 0.f;
                LB[i * LB_STR + lane + 32] = 0.f;
            }
        }
        __syncthreads();

        // GEMM3: ao_h[64,32] = P[64,64] @ v_h[64,32]  -> XS (x is dead)
        {
            const int mt = warp & 3, ng = warp >> 2;
            const int rb = mt * 16;
            float acc[2][4];
#pragma unroll
            for (int t = 0; t < 2; t++) { acc[t][0] = acc[t][1] = acc[t][2] = acc[t][3] = 0.f; }
#pragma unroll
            for (int kk = 0; kk < 8; kk++) {
                const int kc = kk * 8;
                unsigned a0 = F2U(LB[(rb + g)     * LB_STR + kc + tig]);
                unsigned a1 = F2U(LB[(rb + g + 8) * LB_STR + kc + tig]);
                unsigned a2 = F2U(LB[(rb + g)     * LB_STR + kc + tig + 4]);
                unsigned a3 = F2U(LB[(rb + g + 8) * LB_STR + kc + tig + 4]);
#pragma unroll
                for (int t = 0; t < 2; t++) {
                    const int n8 = ng * 2 + t;
                    unsigned b0 = F2U(VB[(kc + tig)     * VB_STR + h * 32 + n8 * 8 + g]);
                    unsigned b1 = F2U(VB[(kc + tig + 4) * VB_STR + h * 32 + n8 * 8 + g]);
                    mma8(acc[t], a0, a1, a2, a3, b0, b1);
                }
            }
#pragma unroll
            for (int t = 0; t < 2; t++) {
                const int n8 = ng * 2 + t;
                const int c0 = h * 32 + n8 * 8 + 2 * tig;
                XS[(rb + g)     * XS_STR + c0]     = tfs(acc[t][0]);
                XS[(rb + g)     * XS_STR + c0 + 1] = tfs(acc[t][1]);
                XS[(rb + g + 8) * XS_STR + c0]     = tfs(acc[t][2]);
                XS[(rb + g + 8) * XS_STR + c0 + 1] = tfs(acc[t][3]);
            }
        }
        __syncthreads();
    }

    // ---------------- GEMM4: y[64,128] = ao[64,128] @ proj_w + b -----------
    {
        float acc[8][4];
#pragma unroll
        for (int t = 0; t < 8; t++) { acc[t][0] = acc[t][1] = acc[t][2] = acc[t][3] = 0.f; }
        const int mt = warp & 3, ng = warp >> 2;
        const int rb = mt * 16;

        for (int kk = 0; kk < 8; kk++) {
            const float4* wg = reinterpret_cast<const float4*>(proj_w + (size_t)kk * 16 * CDIM);
            for (int idx = tid; idx < 16 * 32; idx += 256) {
                int r = idx >> 5, c4 = idx & 31;
                float4 v = wg[r * 32 + c4];
                float* d = WSm + r * WP_STR + c4 * 4;
                d[0] = tfs(v.x); d[1] = tfs(v.y); d[2] = tfs(v.z); d[3] = tfs(v.w);
            }
            __syncthreads();
#pragma unroll
            for (int k2 = 0; k2 < 2; k2++) {
                const int kc = kk * 16 + k2 * 8;
                unsigned a0 = F2U(XS[(rb + g)     * XS_STR + kc + tig]);
                unsigned a1 = F2U(XS[(rb + g + 8) * XS_STR + kc + tig]);
                unsigned a2 = F2U(XS[(rb + g)     * XS_STR + kc + tig + 4]);
                unsigned a3 = F2U(XS[(rb + g + 8) * XS_STR + kc + tig + 4]);
#pragma unroll
                for (int t = 0; t < 8; t++) {
                    const int n8 = ng * 8 + t;
                    unsigned b0 = F2U(WSm[(k2 * 8 + tig)     * WP_STR + n8 * 8 + g]);
                    unsigned b1 = F2U(WSm[(k2 * 8 + tig + 4) * WP_STR + n8 * 8 + g]);
                    mma8(acc[t], a0, a1, a2, a3, b0, b1);
                }
            }
            __syncthreads();
        }
        // epilogue -> YS (reuse QK region, stride 132), +proj_b
        float* YS = QK;
#pragma unroll
        for (int t = 0; t < 8; t++) {
            const int n8 = ng * 8 + t;
            const int c0 = n8 * 8 + 2 * tig;
            const float b0 = proj_b[c0], b1 = proj_b[c0 + 1];
            YS[(rb + g)     * XS_STR + c0]     = acc[t][0] + b0;
            YS[(rb + g)     * XS_STR + c0 + 1] = acc[t][1] + b1;
            YS[(rb + g + 8) * XS_STR + c0]     = acc[t][2] + b0;
            YS[(rb + g + 8) * XS_STR + c0 + 1] = acc[t][3] + b1;
        }
    }
    __syncthreads();

    // ---------------- store rows 0..48 -------------------------------------
    {
        const float* YS = QK;
        float4* og = reinterpret_cast<float4*>(out + (size_t)w * NTOK * CDIM);
        for (int idx = tid; idx < NTOK * 32; idx += 256) {
            int r = idx >> 5, c4 = idx & 31;
            const float* p = YS + r * XS_STR + c4 * 4;
            og[r * 32 + c4] = make_float4(p[0], p[1], p[2], p[3]);
        }
    }
}

extern "C" void kernel_launch(void* const* d_in, const int* in_sizes, int n_in,
                              void* d_out, int out_size) {
    const float* x      = (const float*)d_in[0];
    const float* qkv_w  = (const float*)d_in[1];
    const float* qkv_b  = (const float*)d_in[2];
    const float* proj_w = (const float*)d_in[3];
    const float* proj_b = (const float*)d_in[4];
    const float* bias_t = (const float*)d_in[5];
    const float* mask   = (const float*)d_in[6];
    float* out = (float*)d_out;

    const int bw    = in_sizes[0] / (NTOK * CDIM);      // 4096 windows
    const int nmask = in_sizes[6] / (NTOK * NTOK);      // 64

    const size_t smem = SMEM_FLOATS * sizeof(float);    // 189972 B
    cudaFuncSetAttribute(win_attn_kernel,
                         cudaFuncAttributeMaxDynamicSharedMemorySize, (int)smem);
    win_attn_kernel<<<bw, 256, smem>>>(x, qkv_w, qkv_b, proj_w, proj_b,
                                       bias_t, mask, out, nmask);
}

// round 2
// speedup vs baseline: 1.5479x; 1.5479x over previous
#include <cuda_runtime.h>
#include <cstdint>

// ---------------------------------------------------------------------------
// Swin WindowAttention, fused per-window kernel, TF32 mma.sync (m16n8k8).
// Round 2: 512 threads (16 warps), parallel heads, 4 weight k-slices.
// One CTA per window. Token dim padded 49 -> 64.
// ---------------------------------------------------------------------------

namespace {
constexpr int NTOK  = 49;
constexpr int CDIM  = 128;
constexpr int NHEAD = 4;
constexpr int TC3   = 384;

// Strides (floats): A-frag pattern needs stride%32==4, B-frag needs %32==8.
constexpr int XS_STR = 132;  // x / attn-out   [64][132]  (A operand)
constexpr int Q_STR  = 132;  // q              [64][132]  (A operand)
constexpr int K_STR  = 132;  // k              [64][132]  (B via row(g) -> %32==4)
constexpr int V_STR  = 136;  // v              [64][136]  (B operand)
constexpr int WS_STR = 392;  // qkv_w slice    [32][392]  (B operand)
constexpr int WP_STR = 136;  // proj_w slice   [32][136]  (B operand)
constexpr int LB_STR = 68;   // logits per head [64][68]  (A operand)
constexpr int LB_SZ  = 64 * LB_STR;              // 4352

constexpr int OFF_XS = 0;                        // 8448
constexpr int OFF_Q  = OFF_XS + 64 * XS_STR;     // 8448
constexpr int OFF_K  = OFF_Q  + 64 * Q_STR;      // 16896
constexpr int OFF_V  = OFF_K  + 64 * K_STR;      // 25344
constexpr int OFF_LB = OFF_V  + 64 * V_STR;      // 34048  (4 heads = 17408; WS/WP alias here)
constexpr int OFF_MS = OFF_LB + NHEAD * LB_SZ;   // 51456
constexpr int OFF_BT = OFF_MS + NTOK * NTOK;     // 53857
constexpr int SMEM_FLOATS = OFF_BT + 169 * NHEAD;// 54533 floats = 218132 B
}

__device__ __forceinline__ float tfs(float f) {
    unsigned r;
    asm("cvt.rna.tf32.f32 %0, %1;" : "=r"(r) : "f"(f));
    return __uint_as_float(r);
}

__device__ __forceinline__ void mma8(float* c,
                                     unsigned a0, unsigned a1, unsigned a2, unsigned a3,
                                     unsigned b0, unsigned b1) {
    asm volatile(
        "mma.sync.aligned.m16n8k8.row.col.f32.tf32.tf32.f32 "
        "{%0,%1,%2,%3}, {%4,%5,%6,%7}, {%8,%9}, {%0,%1,%2,%3};"
        : "+f"(c[0]), "+f"(c[1]), "+f"(c[2]), "+f"(c[3])
        : "r"(a0), "r"(a1), "r"(a2), "r"(a3), "r"(b0), "r"(b1));
}

#define F2U(x) __float_as_uint(x)

__global__ __launch_bounds__(512, 1) void win_attn_kernel(
    const float* __restrict__ x,       const float* __restrict__ qkv_w,
    const float* __restrict__ qkv_b,   const float* __restrict__ proj_w,
    const float* __restrict__ proj_b,  const float* __restrict__ bias_t,
    const float* __restrict__ mask,    float* __restrict__ out,
    int nmask)
{
    extern __shared__ float sm[];
    float* XS = sm + OFF_XS;
    float* Qb = sm + OFF_Q;
    float* Kb = sm + OFF_K;
    float* Vb = sm + OFF_V;
    float* LB = sm + OFF_LB;     // also aliases WS (GEMM1) and WP (GEMM4)
    float* MS = sm + OFF_MS;
    float* BT = sm + OFF_BT;
    float* WSm = LB;             // [32][392] = 12544 <= 17408
    float* WPm = LB;             // [32][136] = 4352

    const int w    = blockIdx.x;
    const int tid  = threadIdx.x;
    const int warp = tid >> 5;
    const int lane = tid & 31;
    const int g    = lane >> 2;
    const int tig  = lane & 3;

    // ---------------- Phase 0: load x, mask, bias table --------------------
    {
        const float4* xg = reinterpret_cast<const float4*>(x + (size_t)w * NTOK * CDIM);
        for (int idx = tid; idx < NTOK * 32; idx += 512) {
            int r = idx >> 5, c4 = idx & 31;
            float4 v = xg[r * 32 + c4];
            float* d = XS + r * XS_STR + c4 * 4;
            d[0] = tfs(v.x); d[1] = tfs(v.y); d[2] = tfs(v.z); d[3] = tfs(v.w);
        }
        for (int idx = tid; idx < 15 * XS_STR; idx += 512)
            XS[NTOK * XS_STR + idx] = 0.0f;

        const float* mg = mask + (size_t)(w % nmask) * NTOK * NTOK;
        for (int idx = tid; idx < NTOK * NTOK; idx += 512) MS[idx] = mg[idx];
        for (int idx = tid; idx < 169 * NHEAD; idx += 512) BT[idx] = bias_t[idx];
    }
    __syncthreads();

    // ---------------- GEMM1: qkv[64,384] = XS[64,128] @ qkv_w + b ----------
    {
        float acc[12][4];
#pragma unroll
        for (int t = 0; t < 12; t++) { acc[t][0] = acc[t][1] = acc[t][2] = acc[t][3] = 0.f; }
        const int mt = warp & 3, ng = warp >> 2;
        const int rb = mt * 16;

        for (int s = 0; s < 4; s++) {
            // stage qkv_w rows [s*32, s*32+32) x [0,384) -> WSm, tf32-rounded
            const float4* wg = reinterpret_cast<const float4*>(qkv_w + (size_t)s * 32 * TC3);
            for (int idx = tid; idx < 32 * 96; idx += 512) {
                int r = idx / 96, c4 = idx % 96;
                float4 v = wg[r * 96 + c4];
                float* d = WSm + r * WS_STR + c4 * 4;
                d[0] = tfs(v.x); d[1] = tfs(v.y); d[2] = tfs(v.z); d[3] = tfs(v.w);
            }
            __syncthreads();
#pragma unroll
            for (int k2 = 0; k2 < 4; k2++) {
                const int kc = s * 32 + k2 * 8;
                unsigned a0 = F2U(XS[(rb + g)     * XS_STR + kc + tig]);
                unsigned a1 = F2U(XS[(rb + g + 8) * XS_STR + kc + tig]);
                unsigned a2 = F2U(XS[(rb + g)     * XS_STR + kc + tig + 4]);
                unsigned a3 = F2U(XS[(rb + g + 8) * XS_STR + kc + tig + 4]);
#pragma unroll
                for (int t = 0; t < 12; t++) {
                    const int n8 = ng * 12 + t;
                    unsigned b0 = F2U(WSm[(k2 * 8 + tig)     * WS_STR + n8 * 8 + g]);
                    unsigned b1 = F2U(WSm[(k2 * 8 + tig + 4) * WS_STR + n8 * 8 + g]);
                    mma8(acc[t], a0, a1, a2, a3, b0, b1);
                }
            }
            __syncthreads();
        }
        // epilogue: +bias, scale q, split into Q / K / V, tf32-rounded
        const float scale = 0.17677669529663687f;  // 32^-0.5
#pragma unroll
        for (int t = 0; t < 12; t++) {
            const int n8 = ng * 12 + t;
            const int c0 = n8 * 8 + 2 * tig, c1 = c0 + 1;
            const int r0 = rb + g, r1 = rb + g + 8;
            const float bb0 = qkv_b[c0], bb1 = qkv_b[c1];
            float v00 = acc[t][0] + bb0, v01 = acc[t][1] + bb1;
            float v10 = acc[t][2] + bb0, v11 = acc[t][3] + bb1;
            if (c0 < 128) {
                v00 *= scale; v01 *= scale; v10 *= scale; v11 *= scale;
                Qb[r0 * Q_STR + c0] = tfs(v00); Qb[r0 * Q_STR + c1] = tfs(v01);
                Qb[r1 * Q_STR + c0] = tfs(v10); Qb[r1 * Q_STR + c1] = tfs(v11);
            } else if (c0 < 256) {
                Kb[r0 * K_STR + c0 - 128] = tfs(v00); Kb[r0 * K_STR + c1 - 128] = tfs(v01);
                Kb[r1 * K_STR + c0 - 128] = tfs(v10); Kb[r1 * K_STR + c1 - 128] = tfs(v11);
            } else {
                Vb[r0 * V_STR + c0 - 256] = tfs(v00); Vb[r0 * V_STR + c1 - 256] = tfs(v01);
                Vb[r1 * V_STR + c0 - 256] = tfs(v10); Vb[r1 * V_STR + c1 - 256] = tfs(v11);
            }
        }
    }
    __syncthreads();

    // ---------------- Attention: all 4 heads in parallel -------------------
    const int h  = warp >> 2;         // head for this warp
    const int mt = warp & 3;          // M-tile for this warp
    const int rb = mt * 16;
    float* LBh = LB + h * LB_SZ;

    // GEMM2: logits_h[64,64] = q_h[64,32] @ k_h[64,32]^T
    {
        float acc[8][4];
#pragma unroll
        for (int t = 0; t < 8; t++) { acc[t][0] = acc[t][1] = acc[t][2] = acc[t][3] = 0.f; }
#pragma unroll
        for (int kk = 0; kk < 4; kk++) {
            const int kc = h * 32 + kk * 8;
            unsigned a0 = F2U(Qb[(rb + g)     * Q_STR + kc + tig]);
            unsigned a1 = F2U(Qb[(rb + g + 8) * Q_STR + kc + tig]);
            unsigned a2 = F2U(Qb[(rb + g)     * Q_STR + kc + tig + 4]);
            unsigned a3 = F2U(Qb[(rb + g + 8) * Q_STR + kc + tig + 4]);
#pragma unroll
            for (int t = 0; t < 8; t++) {
                unsigned b0 = F2U(Kb[(t * 8 + g) * K_STR + kc + tig]);
                unsigned b1 = F2U(Kb[(t * 8 + g) * K_STR + kc + tig + 4]);
                mma8(acc[t], a0, a1, a2, a3, b0, b1);
            }
        }
#pragma unroll
        for (int t = 0; t < 8; t++) {
            const int c0 = t * 8 + 2 * tig;
            LBh[(rb + g)     * LB_STR + c0]     = acc[t][0];
            LBh[(rb + g)     * LB_STR + c0 + 1] = acc[t][1];
            LBh[(rb + g + 8) * LB_STR + c0]     = acc[t][2];
            LBh[(rb + g + 8) * LB_STR + c0 + 1] = acc[t][3];
        }
    }
    __syncthreads();

    // softmax: 64 rows per head, 4 warps per head -> 16 rows each
    for (int rr = 0; rr < 16; rr++) {
        const int i = mt + rr * 4;
        if (i < NTOK) {
            const int ri = i / 7, ci = i - ri * 7;
            float v1, v2;
            {
                const int j = lane;               // always < 49
                const int rj = j / 7, cj = j - rj * 7;
                const int idx = (ri - rj + 6) * 13 + (ci - cj + 6);
                v1 = LBh[i * LB_STR + j] + BT[idx * NHEAD + h] + MS[i * NTOK + j];
            }
            const int j2 = lane + 32;
            if (j2 < NTOK) {
                const int rj = j2 / 7, cj = j2 - rj * 7;
                const int idx = (ri - rj + 6) * 13 + (ci - cj + 6);
                v2 = LBh[i * LB_STR + j2] + BT[idx * NHEAD + h] + MS[i * NTOK + j2];
            } else {
                v2 = -3.0e38f;
            }
            float m = fmaxf(v1, v2);
#pragma unroll
            for (int o = 16; o > 0; o >>= 1) m = fmaxf(m, __shfl_xor_sync(0xffffffffu, m, o));
            float e1 = __expf(v1 - m);
            float e2 = (j2 < NTOK) ? __expf(v2 - m) : 0.f;
            float s = e1 + e2;
#pragma unroll
            for (int o = 16; o > 0; o >>= 1) s += __shfl_xor_sync(0xffffffffu, s, o);
            const float inv = 1.0f / s;
            LBh[i * LB_STR + lane] = tfs(e1 * inv);
            LBh[i * LB_STR + j2]   = (j2 < NTOK) ? tfs(e2 * inv) : 0.f;
        } else {
            LBh[i * LB_STR + lane]      = 0.f;
            LBh[i * LB_STR + lane + 32] = 0.f;
        }
    }
    __syncthreads();

    // GEMM3: ao_h[64,32] = P_h[64,64] @ v_h[64,32]  -> XS (x is dead)
    {
        float acc[4][4];
#pragma unroll
        for (int t = 0; t < 4; t++) { acc[t][0] = acc[t][1] = acc[t][2] = acc[t][3] = 0.f; }
#pragma unroll
        for (int kk = 0; kk < 8; kk++) {
            const int kc = kk * 8;
            unsigned a0 = F2U(LBh[(rb + g)     * LB_STR + kc + tig]);
            unsigned a1 = F2U(LBh[(rb + g + 8) * LB_STR + kc + tig]);
            unsigned a2 = F2U(LBh[(rb + g)     * LB_STR + kc + tig + 4]);
            unsigned a3 = F2U(LBh[(rb + g + 8) * LB_STR + kc + tig + 4]);
#pragma unroll
            for (int t = 0; t < 4; t++) {
                unsigned b0 = F2U(Vb[(kc + tig)     * V_STR + h * 32 + t * 8 + g]);
                unsigned b1 = F2U(Vb[(kc + tig + 4) * V_STR + h * 32 + t * 8 + g]);
                mma8(acc[t], a0, a1, a2, a3, b0, b1);
            }
        }
#pragma unroll
        for (int t = 0; t < 4; t++) {
            const int c0 = h * 32 + t * 8 + 2 * tig;
            XS[(rb + g)     * XS_STR + c0]     = tfs(acc[t][0]);
            XS[(rb + g)     * XS_STR + c0 + 1] = tfs(acc[t][1]);
            XS[(rb + g + 8) * XS_STR + c0]     = tfs(acc[t][2]);
            XS[(rb + g + 8) * XS_STR + c0 + 1] = tfs(acc[t][3]);
        }
    }
    __syncthreads();

    // ---------------- GEMM4: y[64,128] = ao[64,128] @ proj_w + b -----------
    {
        float acc[4][4];
#pragma unroll
        for (int t = 0; t < 4; t++) { acc[t][0] = acc[t][1] = acc[t][2] = acc[t][3] = 0.f; }
        const int ng = warp >> 2;

        for (int s = 0; s < 4; s++) {
            const float4* wg = reinterpret_cast<const float4*>(proj_w + (size_t)s * 32 * CDIM);
            for (int idx = tid; idx < 32 * 32; idx += 512) {
                int r = idx >> 5, c4 = idx & 31;
                float4 v = wg[r * 32 + c4];
                float* d = WPm + r * WP_STR + c4 * 4;
                d[0] = tfs(v.x); d[1] = tfs(v.y); d[2] = tfs(v.z); d[3] = tfs(v.w);
            }
            __syncthreads();
#pragma unroll
            for (int k2 = 0; k2 < 4; k2++) {
                const int kc = s * 32 + k2 * 8;
                unsigned a0 = F2U(XS[(rb + g)     * XS_STR + kc + tig]);
                unsigned a1 = F2U(XS[(rb + g + 8) * XS_STR + kc + tig]);
                unsigned a2 = F2U(XS[(rb + g)     * XS_STR + kc + tig + 4]);
                unsigned a3 = F2U(XS[(rb + g + 8) * XS_STR + kc + tig + 4]);
#pragma unroll
                for (int t = 0; t < 4; t++) {
                    const int n8 = ng * 4 + t;
                    unsigned b0 = F2U(WPm[(k2 * 8 + tig)     * WP_STR + n8 * 8 + g]);
                    unsigned b1 = F2U(WPm[(k2 * 8 + tig + 4) * WP_STR + n8 * 8 + g]);
                    mma8(acc[t], a0, a1, a2, a3, b0, b1);
                }
            }
            __syncthreads();
        }
        // epilogue -> YS (reuse Q buffer), +proj_b
        float* YS = Qb;
#pragma unroll
        for (int t = 0; t < 4; t++) {
            const int n8 = ng * 4 + t;
            const int c0 = n8 * 8 + 2 * tig;
            const float b0 = proj_b[c0], b1 = proj_b[c0 + 1];
            YS[(rb + g)     * Q_STR + c0]     = acc[t][0] + b0;
            YS[(rb + g)     * Q_STR + c0 + 1] = acc[t][1] + b1;
            YS[(rb + g + 8) * Q_STR + c0]     = acc[t][2] + b0;
            YS[(rb + g + 8) * Q_STR + c0 + 1] = acc[t][3] + b1;
        }
    }
    __syncthreads();

    // ---------------- store rows 0..48 -------------------------------------
    {
        const float* YS = Qb;
        float4* og = reinterpret_cast<float4*>(out + (size_t)w * NTOK * CDIM);
        for (int idx = tid; idx < NTOK * 32; idx += 512) {
            int r = idx >> 5, c4 = idx & 31;
            const float* p = YS + r * Q_STR + c4 * 4;
            og[r * 32 + c4] = make_float4(p[0], p[1], p[2], p[3]);
        }
    }
}

extern "C" void kernel_launch(void* const* d_in, const int* in_sizes, int n_in,
                              void* d_out, int out_size) {
    const float* x      = (const float*)d_in[0];
    const float* qkv_w  = (const float*)d_in[1];
    const float* qkv_b  = (const float*)d_in[2];
    const float* proj_w = (const float*)d_in[3];
    const float* proj_b = (const float*)d_in[4];
    const float* bias_t = (const float*)d_in[5];
    const float* mask   = (const float*)d_in[6];
    float* out = (float*)d_out;

    const int bw    = in_sizes[0] / (NTOK * CDIM);      // 4096 windows
    const int nmask = in_sizes[6] / (NTOK * NTOK);      // 64

    const size_t smem = SMEM_FLOATS * sizeof(float);    // 218132 B
    cudaFuncSetAttribute(win_attn_kernel,
                         cudaFuncAttributeMaxDynamicSharedMemorySize, (int)smem);
    win_attn_kernel<<<bw, 512, smem>>>(x, qkv_w, qkv_b, proj_w, proj_b,
                                       bias_t, mask, out, nmask);
}

// round 3
// speedup vs baseline: 2.0420x; 1.3191x over previous
#include <cuda_runtime.h>
#include <cstdint>

// ---------------------------------------------------------------------------
// Swin WindowAttention, fused per-window TF32 mma.sync kernel, round 3.
//  - prepack kernel: W transposed+tf32+pair-packed into __device__ globals,
//    rpb+mask combined table RM[v][h][i][j].
//  - main kernel: 512 thr, pair-packed smem (one LDS.64 per fragment pair),
//    GEMM1 sliced n=128 (slice == Q/K/V), register-prefetched W staging.
// ---------------------------------------------------------------------------

namespace {
constexpr int NTOK  = 49;
constexpr int CDIM  = 128;
constexpr int NHEAD = 4;
constexpr int TC3   = 384;
constexpr int MAXW  = 64;     // max mask windows (spec: 64)
constexpr int S136  = 136;    // %32==8  (packed operand stride)
constexpr int S72   = 72;     // %32==8
constexpr int S132  = 132;    // output staging stride

constexpr int OFF_XS = 0;                    // [64][136] x / attn-out (A)
constexpr int OFF_Q  = OFF_XS + 64 * S136;   // [64][136] Q (A of gemm2)
constexpr int OFF_K  = OFF_Q  + 64 * S136;   // [64][136] K (B of gemm2); later Y
constexpr int OFF_VT = OFF_K  + 64 * S136;   // [128][72] V transposed (B of gemm3)
constexpr int OFF_LB = OFF_VT + 128 * S72;   // 4x[64][72] logits; aliases W stage
constexpr int LBH    = 64 * S72;
constexpr int SMEMF  = OFF_LB + NHEAD * LBH; // 53760 floats = 215040 B
}

__device__ float g_wqkv_t[TC3 * CDIM];               // [n=384][pk(k=128)]
__device__ float g_wproj_t[CDIM * CDIM];             // [n=128][pk(k=128)]
__device__ float g_rm[MAXW * NHEAD * NTOK * NTOK];   // rpb + mask combined

// pack permutation within each 8-group: [0,4,1,5,2,6,3,7]
__device__ __host__ __forceinline__ int pk(int c) {
    return (c & ~7) | ((c & 3) << 1) | ((c >> 2) & 1);
}

__device__ __forceinline__ float tfs(float f) {
    unsigned r;
    asm("cvt.rna.tf32.f32 %0, %1;" : "=r"(r) : "f"(f));
    return __uint_as_float(r);
}

__device__ __forceinline__ void mma8(float* c, float a0, float a1, float a2, float a3,
                                     float b0, float b1) {
    asm volatile(
        "mma.sync.aligned.m16n8k8.row.col.f32.tf32.tf32.f32 "
        "{%0,%1,%2,%3}, {%4,%5,%6,%7}, {%8,%9}, {%0,%1,%2,%3};"
        : "+f"(c[0]), "+f"(c[1]), "+f"(c[2]), "+f"(c[3])
        : "r"(__float_as_uint(a0)), "r"(__float_as_uint(a1)),
          "r"(__float_as_uint(a2)), "r"(__float_as_uint(a3)),
          "r"(__float_as_uint(b0)), "r"(__float_as_uint(b1)));
}

// ---------------- prepack: W transpose+pack+tf32 ---------------------------
__global__ void prepack_w(const float* __restrict__ qkv_w,
                          const float* __restrict__ proj_w) {
    int t = blockIdx.x * blockDim.x + threadIdx.x;
    if (t < TC3 * CDIM) {                      // t over (k, n), n fastest
        int n = t % TC3, k = t / TC3;
        g_wqkv_t[n * CDIM + pk(k)] = tfs(qkv_w[k * TC3 + n]);
    } else {
        int t2 = t - TC3 * CDIM;
        if (t2 < CDIM * CDIM) {
            int n = t2 % CDIM, k = t2 / CDIM;
            g_wproj_t[n * CDIM + pk(k)] = tfs(proj_w[k * CDIM + n]);
        }
    }
}

// ---------------- prepack: rpb + mask table --------------------------------
__global__ void prepack_rm(const float* __restrict__ mask,
                           const float* __restrict__ bias_t, int nmask) {
    int t = blockIdx.x * blockDim.x + threadIdx.x;
    int total = nmask * NHEAD * NTOK * NTOK;
    if (t >= total) return;
    int j = t % NTOK;
    int i = (t / NTOK) % NTOK;
    int h = (t / (NTOK * NTOK)) % NHEAD;
    int v = t / (NTOK * NTOK * NHEAD);
    int ri = i / 7, ci = i - ri * 7;
    int rj = j / 7, cj = j - rj * 7;
    int idx = (ri - rj + 6) * 13 + (ci - cj + 6);
    g_rm[t] = bias_t[idx * NHEAD + h] + mask[(size_t)v * NTOK * NTOK + i * NTOK + j];
}

// ---------------- main kernel ---------------------------------------------
__global__ __launch_bounds__(512, 1) void win_attn_kernel(
    const float* __restrict__ x,      const float* __restrict__ qkv_b,
    const float* __restrict__ proj_b, float* __restrict__ out, int nmask)
{
    extern __shared__ float sm[];
    float* XS = sm + OFF_XS;
    float* Qb = sm + OFF_Q;
    float* Kb = sm + OFF_K;
    float* VT = sm + OFF_VT;
    float* LB = sm + OFF_LB;
    float* WB = LB;                 // W stage buffer aliases LB region

    const int w    = blockIdx.x;
    const int tid  = threadIdx.x;
    const int warp = tid >> 5;
    const int lane = tid & 31;
    const int g    = lane >> 2;
    const int tig  = lane & 3;
    const int mt   = warp & 3;      // M tile (16 rows)
    const int ng   = warp >> 2;     // N group (gemm1/4) == head (gemm2/3)
    const int rb   = mt * 16;
    const int tg2  = tig * 2;

    // ---------------- phase 0: stage x (packed) + zero VT pad cols ---------
    {
        const float* xg = x + (size_t)w * NTOK * CDIM;
        for (int u = tid; u < NTOK * 16; u += 512) {     // 8-float groups
            int r = u >> 4, gb = (u & 15) * 8;
            float4 v0 = *(const float4*)(xg + r * CDIM + gb);
            float4 v1 = *(const float4*)(xg + r * CDIM + gb + 4);
            float* d = XS + r * S136 + gb;
            d[0] = tfs(v0.x); d[1] = tfs(v1.x);
            d[2] = tfs(v0.y); d[3] = tfs(v1.y);
            d[4] = tfs(v0.z); d[5] = tfs(v1.z);
            d[6] = tfs(v0.w); d[7] = tfs(v1.w);
        }
        // zero VT token cols 49..63 (k-dim of gemm3 must be 0)
        for (int u = tid; u < CDIM * 16; u += 512) {
            int ch = u >> 4, t = 48 + (u & 15);
            if (t > 48) VT[ch * S72 + pk(t)] = 0.0f;
        }
    }

    // ---------------- GEMM1: 3 n-slices of 128 (Q, K, V) -------------------
    const float4* wsrc = (const float4*)g_wqkv_t;
    float4 pf[8];
#pragma unroll
    for (int u = 0; u < 8; u++) pf[u] = wsrc[u * 512 + tid];     // slice 0
    __syncthreads();                                             // phase0 done
#pragma unroll
    for (int u = 0; u < 8; u++) {
        int idx = u * 512 + tid, r = idx >> 5, c4 = idx & 31;
        *(float4*)(WB + r * S136 + c4 * 4) = pf[u];
    }
    __syncthreads();

    const float scale = 0.17677669529663687f;  // 32^-0.5

    for (int s = 0; s < 3; s++) {
        if (s < 2) {                                             // prefetch next
#pragma unroll
            for (int u = 0; u < 8; u++) pf[u] = wsrc[(s + 1) * 4096 + u * 512 + tid];
        }
        float acc[4][4];
#pragma unroll
        for (int t = 0; t < 4; t++) acc[t][0] = acc[t][1] = acc[t][2] = acc[t][3] = 0.f;

#pragma unroll 4
        for (int kk = 0; kk < 16; kk++) {
            const int kc = kk * 8;
            float2 aA = *(float2*)(XS + (rb + g)     * S136 + kc + tg2);
            float2 aB = *(float2*)(XS + (rb + g + 8) * S136 + kc + tg2);
#pragma unroll
            for (int t = 0; t < 4; t++) {
                float2 b = *(float2*)(WB + (ng * 32 + t * 8 + g) * S136 + kc + tg2);
                mma8(acc[t], aA.x, aB.x, aA.y, aB.y, b.x, b.y);
            }
        }
        // epilogue (specialized per slice)
        const int r0 = rb + g, r1 = rb + g + 8;
#pragma unroll
        for (int t = 0; t < 4; t++) {
            const int c0 = ng * 32 + t * 8 + tg2;                // local n (0..127)
            const float bb0 = qkv_b[s * 128 + c0], bb1 = qkv_b[s * 128 + c0 + 1];
            float v00 = acc[t][0] + bb0, v01 = acc[t][1] + bb1;
            float v10 = acc[t][2] + bb0, v11 = acc[t][3] + bb1;
            if (s == 0) {          // Q (scaled), packed [tok][pk(ch)]
                Qb[r0 * S136 + pk(c0)]     = tfs(v00 * scale);
                Qb[r0 * S136 + pk(c0 + 1)] = tfs(v01 * scale);
                Qb[r1 * S136 + pk(c0)]     = tfs(v10 * scale);
                Qb[r1 * S136 + pk(c0 + 1)] = tfs(v11 * scale);
            } else if (s == 1) {   // K, packed [tok][pk(ch)]
                Kb[r0 * S136 + pk(c0)]     = tfs(v00);
                Kb[r0 * S136 + pk(c0 + 1)] = tfs(v01);
                Kb[r1 * S136 + pk(c0)]     = tfs(v10);
                Kb[r1 * S136 + pk(c0 + 1)] = tfs(v11);
            } else {               // V transposed: [ch][pk(tok)], pad rows skipped
                if (r0 < NTOK) {
                    VT[c0 * S72 + pk(r0)]       = tfs(v00);
                    VT[(c0 + 1) * S72 + pk(r0)] = tfs(v01);
                }
                if (r1 < NTOK) {
                    VT[c0 * S72 + pk(r1)]       = tfs(v10);
                    VT[(c0 + 1) * S72 + pk(r1)] = tfs(v11);
                }
            }
        }
        __syncthreads();
        if (s < 2) {
#pragma unroll
            for (int u = 0; u < 8; u++) {
                int idx = u * 512 + tid, r = idx >> 5, c4 = idx & 31;
                *(float4*)(WB + r * S136 + c4 * 4) = pf[u];
            }
            __syncthreads();
        }
    }

    // ---------------- GEMM2: logits_h[64,64] = Q_h @ K_h^T ------------------
    const int h = ng;                        // head for attention phase
    float* LBh = LB + h * LBH;
    {
        float acc[8][4];
#pragma unroll
        for (int t = 0; t < 8; t++) acc[t][0] = acc[t][1] = acc[t][2] = acc[t][3] = 0.f;
#pragma unroll
        for (int kk = 0; kk < 4; kk++) {
            const int kc = h * 32 + kk * 8;
            float2 aA = *(float2*)(Qb + (rb + g)     * S136 + kc + tg2);
            float2 aB = *(float2*)(Qb + (rb + g + 8) * S136 + kc + tg2);
#pragma unroll
            for (int t = 0; t < 8; t++) {
                float2 b = *(float2*)(Kb + (t * 8 + g) * S136 + kc + tg2);
                mma8(acc[t], aA.x, aB.x, aA.y, aB.y, b.x, b.y);
            }
        }
#pragma unroll
        for (int t = 0; t < 8; t++) {
            const int c0 = t * 8 + tg2;
            LBh[(rb + g)     * S72 + pk(c0)]     = acc[t][0];
            LBh[(rb + g)     * S72 + pk(c0 + 1)] = acc[t][1];
            LBh[(rb + g + 8) * S72 + pk(c0)]     = acc[t][2];
            LBh[(rb + g + 8) * S72 + pk(c0 + 1)] = acc[t][3];
        }
    }
    __syncthreads();

    // ---------------- softmax (+precombined rpb+mask via g_rm) -------------
    {
        const int v = w % nmask;
        const float* rmh = g_rm + ((size_t)(v * NHEAD + h)) * NTOK * NTOK;
        for (int i = mt; i < NTOK; i += 4) {
            const float* rm = rmh + i * NTOK;
            const int j2 = lane + 32;
            const bool ok2 = j2 < NTOK;
            float m1 = rm[lane];
            float m2 = ok2 ? rm[j2] : 0.f;
            float v1 = LBh[i * S72 + pk(lane)] + m1;
            float v2 = ok2 ? (LBh[i * S72 + pk(j2)] + m2) : -3.0e38f;
            float mx = fmaxf(v1, v2);
#pragma unroll
            for (int o = 16; o > 0; o >>= 1) mx = fmaxf(mx, __shfl_xor_sync(0xffffffffu, mx, o));
            float e1 = __expf(v1 - mx);
            float e2 = ok2 ? __expf(v2 - mx) : 0.f;
            float ssum = e1 + e2;
#pragma unroll
            for (int o = 16; o > 0; o >>= 1) ssum += __shfl_xor_sync(0xffffffffu, ssum, o);
            const float inv = 1.0f / ssum;
            LBh[i * S72 + pk(lane)] = tfs(e1 * inv);
            LBh[i * S72 + pk(j2)]   = ok2 ? tfs(e2 * inv) : 0.f;
        }
    }
    __syncthreads();

    // ---------------- GEMM3: ao_h[64,32] = P_h[64,64] @ V_h ----------------
    {
        float acc[4][4];
#pragma unroll
        for (int t = 0; t < 4; t++) acc[t][0] = acc[t][1] = acc[t][2] = acc[t][3] = 0.f;
#pragma unroll
        for (int kk = 0; kk < 8; kk++) {
            const int kc = kk * 8;
            float2 aA = *(float2*)(LBh + (rb + g)     * S72 + kc + tg2);
            float2 aB = *(float2*)(LBh + (rb + g + 8) * S72 + kc + tg2);
#pragma unroll
            for (int t = 0; t < 4; t++) {
                float2 b = *(float2*)(VT + (h * 32 + t * 8 + g) * S72 + kc + tg2);
                mma8(acc[t], aA.x, aB.x, aA.y, aB.y, b.x, b.y);
            }
        }
        // attn-out -> XS (packed A for gemm4)
#pragma unroll
        for (int t = 0; t < 4; t++) {
            const int c0 = h * 32 + t * 8 + tg2;
            XS[(rb + g)     * S136 + pk(c0)]     = tfs(acc[t][0]);
            XS[(rb + g)     * S136 + pk(c0 + 1)] = tfs(acc[t][1]);
            XS[(rb + g + 8) * S136 + pk(c0)]     = tfs(acc[t][2]);
            XS[(rb + g + 8) * S136 + pk(c0 + 1)] = tfs(acc[t][3]);
        }
    }
    // prefetch proj weights (LB region still owned by gemm3 until barrier)
    {
        const float4* psrc = (const float4*)g_wproj_t;
#pragma unroll
        for (int u = 0; u < 8; u++) pf[u] = psrc[u * 512 + tid];
    }
    __syncthreads();
#pragma unroll
    for (int u = 0; u < 8; u++) {
        int idx = u * 512 + tid, r = idx >> 5, c4 = idx & 31;
        *(float4*)(WB + r * S136 + c4 * 4) = pf[u];
    }
    __syncthreads();

    // ---------------- GEMM4: y[64,128] = ao @ proj_w + b -------------------
    {
        float acc[4][4];
#pragma unroll
        for (int t = 0; t < 4; t++) acc[t][0] = acc[t][1] = acc[t][2] = acc[t][3] = 0.f;
#pragma unroll 4
        for (int kk = 0; kk < 16; kk++) {
            const int kc = kk * 8;
            float2 aA = *(float2*)(XS + (rb + g)     * S136 + kc + tg2);
            float2 aB = *(float2*)(XS + (rb + g + 8) * S136 + kc + tg2);
#pragma unroll
            for (int t = 0; t < 4; t++) {
                float2 b = *(float2*)(WB + (ng * 32 + t * 8 + g) * S136 + kc + tg2);
                mma8(acc[t], aA.x, aB.x, aA.y, aB.y, b.x, b.y);
            }
        }
        // epilogue -> Y (reuse K region, stride 132, unpacked)
        float* Y = Kb;
#pragma unroll
        for (int t = 0; t < 4; t++) {
            const int c0 = ng * 32 + t * 8 + tg2;
            const float b0 = proj_b[c0], b1 = proj_b[c0 + 1];
            Y[(rb + g)     * S132 + c0]     = acc[t][0] + b0;
            Y[(rb + g)     * S132 + c0 + 1] = acc[t][1] + b1;
            Y[(rb + g + 8) * S132 + c0]     = acc[t][2] + b0;
            Y[(rb + g + 8) * S132 + c0 + 1] = acc[t][3] + b1;
        }
    }
    __syncthreads();

    // ---------------- store --------------------------------------------------
    {
        const float* Y = Kb;
        float4* og = (float4*)(out + (size_t)w * NTOK * CDIM);
        for (int idx = tid; idx < NTOK * 32; idx += 512) {
            int r = idx >> 5, c4 = idx & 31;
            const float* p = Y + r * S132 + c4 * 4;
            og[r * 32 + c4] = make_float4(p[0], p[1], p[2], p[3]);
        }
    }
}

extern "C" void kernel_launch(void* const* d_in, const int* in_sizes, int n_in,
                              void* d_out, int out_size) {
    const float* x      = (const float*)d_in[0];
    const float* qkv_w  = (const float*)d_in[1];
    const float* qkv_b  = (const float*)d_in[2];
    const float* proj_w = (const float*)d_in[3];
    const float* proj_b = (const float*)d_in[4];
    const float* bias_t = (const float*)d_in[5];
    const float* mask   = (const float*)d_in[6];
    float* out = (float*)d_out;

    const int bw    = in_sizes[0] / (NTOK * CDIM);   // 4096
    const int nmask = in_sizes[6] / (NTOK * NTOK);   // 64

    prepack_w<<<(TC3 * CDIM + CDIM * CDIM + 255) / 256, 256>>>(qkv_w, proj_w);
    {
        int total = nmask * NHEAD * NTOK * NTOK;
        prepack_rm<<<(total + 255) / 256, 256>>>(mask, bias_t, nmask);
    }

    const size_t smem = SMEMF * sizeof(float);       // 215040 B
    cudaFuncSetAttribute(win_attn_kernel,
                         cudaFuncAttributeMaxDynamicSharedMemorySize, (int)smem);
    win_attn_kernel<<<bw, 512, smem>>>(x, qkv_b, proj_b, out, nmask);
}

// round 4
// speedup vs baseline: 2.1608x; 1.0582x over previous
#include <cuda_runtime.h>
#include <cstdint>

// ---------------------------------------------------------------------------
// Swin WindowAttention, fused per-window TF32 mma.sync kernel, round 4.
// 1024 threads (32 warps, 8/SMSP). Pair-packed smem fragments (LDS.64),
// prepacked weights + combined rpb+mask table, 8-lane-segment softmax.
// ---------------------------------------------------------------------------

namespace {
constexpr int NTOK  = 49;
constexpr int CDIM  = 128;
constexpr int NHEAD = 4;
constexpr int TC3   = 384;
constexpr int MAXW  = 64;
constexpr int S136  = 136;   // %32==8 packed operand stride
constexpr int S72   = 72;    // %32==8
constexpr int S132  = 132;   // output staging stride

constexpr int OFF_XS = 0;                    // [64][136] x / attn-out (A)
constexpr int OFF_Q  = OFF_XS + 64 * S136;   // [64][136] Q
constexpr int OFF_K  = OFF_Q  + 64 * S136;   // [64][136] K; later Y
constexpr int OFF_VT = OFF_K  + 64 * S136;   // [128][72] V transposed
constexpr int OFF_LB = OFF_VT + 128 * S72;   // 4x[64][72] logits; aliases W stage
constexpr int LBH    = 64 * S72;
constexpr int SMEMF  = OFF_LB + NHEAD * LBH; // 53760 floats = 215040 B
}

__device__ float g_wqkv_t[TC3 * CDIM];               // [n=384][pk(k=128)]
__device__ float g_wproj_t[CDIM * CDIM];             // [n=128][pk(k=128)]
__device__ float g_rm[MAXW * NHEAD * NTOK * NTOK];   // rpb + mask combined

// pack permutation within each 8-group: [0,4,1,5,2,6,3,7]
__device__ __host__ __forceinline__ int pk(int c) {
    return (c & ~7) | ((c & 3) << 1) | ((c >> 2) & 1);
}

__device__ __forceinline__ float tfs(float f) {
    unsigned r;
    asm("cvt.rna.tf32.f32 %0, %1;" : "=r"(r) : "f"(f));
    return __uint_as_float(r);
}

__device__ __forceinline__ void mma8(float* c, float a0, float a1, float a2, float a3,
                                     float b0, float b1) {
    asm volatile(
        "mma.sync.aligned.m16n8k8.row.col.f32.tf32.tf32.f32 "
        "{%0,%1,%2,%3}, {%4,%5,%6,%7}, {%8,%9}, {%0,%1,%2,%3};"
        : "+f"(c[0]), "+f"(c[1]), "+f"(c[2]), "+f"(c[3])
        : "r"(__float_as_uint(a0)), "r"(__float_as_uint(a1)),
          "r"(__float_as_uint(a2)), "r"(__float_as_uint(a3)),
          "r"(__float_as_uint(b0)), "r"(__float_as_uint(b1)));
}

// ---------------- prepack kernels ------------------------------------------
__global__ void prepack_w(const float* __restrict__ qkv_w,
                          const float* __restrict__ proj_w) {
    int t = blockIdx.x * blockDim.x + threadIdx.x;
    if (t < TC3 * CDIM) {
        int n = t % TC3, k = t / TC3;
        g_wqkv_t[n * CDIM + pk(k)] = tfs(qkv_w[k * TC3 + n]);
    } else {
        int t2 = t - TC3 * CDIM;
        if (t2 < CDIM * CDIM) {
            int n = t2 % CDIM, k = t2 / CDIM;
            g_wproj_t[n * CDIM + pk(k)] = tfs(proj_w[k * CDIM + n]);
        }
    }
}

__global__ void prepack_rm(const float* __restrict__ mask,
                           const float* __restrict__ bias_t, int nmask) {
    int t = blockIdx.x * blockDim.x + threadIdx.x;
    int total = nmask * NHEAD * NTOK * NTOK;
    if (t >= total) return;
    int j = t % NTOK;
    int i = (t / NTOK) % NTOK;
    int h = (t / (NTOK * NTOK)) % NHEAD;
    int v = t / (NTOK * NTOK * NHEAD);
    int ri = i / 7, ci = i - ri * 7;
    int rj = j / 7, cj = j - rj * 7;
    int idx = (ri - rj + 6) * 13 + (ci - cj + 6);
    g_rm[t] = bias_t[idx * NHEAD + h] + mask[(size_t)v * NTOK * NTOK + i * NTOK + j];
}

// ---------------- main kernel ---------------------------------------------
__global__ __launch_bounds__(1024, 1) void win_attn_kernel(
    const float* __restrict__ x,      const float* __restrict__ qkv_b,
    const float* __restrict__ proj_b, float* __restrict__ out, int nmask)
{
    extern __shared__ float sm[];
    float* XS = sm + OFF_XS;
    float* Qb = sm + OFF_Q;
    float* Kb = sm + OFF_K;
    float* VT = sm + OFF_VT;
    float* LB = sm + OFF_LB;
    float* WB = LB;                 // W stage aliases LB region

    const int w    = blockIdx.x;
    const int tid  = threadIdx.x;
    const int warp = tid >> 5;
    const int lane = tid & 31;
    const int g    = lane >> 2;
    const int tig  = lane & 3;
    const int tg2  = tig * 2;

    // partitions
    const int mt  = warp & 3;       // GEMM1/4: M tile
    const int ngg = warp >> 2;      // GEMM1/4: N group of 16 (0..7)
    const int rb  = mt * 16;
    const int h   = warp >> 3;      // GEMM2/3/softmax: head
    const int wg  = warp & 7;       //   warp-in-head
    const int mt2 = wg & 3;         //   M tile
    const int ng2 = wg >> 2;        //   N group (0..1)
    const int rb2 = mt2 * 16;
    float* LBh = LB + h * LBH;

    // ---------------- phase 0: stage x packed; zero pads --------------------
    {
        const float* xg = x + (size_t)w * NTOK * CDIM;
        if (tid < NTOK * 16) {
            int r = tid >> 4, gb = (tid & 15) * 8;
            float4 v0 = *(const float4*)(xg + r * CDIM + gb);
            float4 v1 = *(const float4*)(xg + r * CDIM + gb + 4);
            float* d = XS + r * S136 + gb;
            *(float4*)(d)     = make_float4(tfs(v0.x), tfs(v1.x), tfs(v0.y), tfs(v1.y));
            *(float4*)(d + 4) = make_float4(tfs(v0.z), tfs(v1.z), tfs(v0.w), tfs(v1.w));
        }
        for (int u = tid; u < 15 * S136; u += 1024)        // XS pad rows = 0
            XS[NTOK * S136 + u] = 0.0f;
        for (int u = tid; u < CDIM * 16; u += 1024) {      // VT pad token cols = 0
            int ch = u >> 4, t = 48 + (u & 15);
            if (t > 48) VT[ch * S72 + pk(t)] = 0.0f;
        }
    }

    // ---------------- GEMM1: 3 n-slices of 128 (Q, K, V) -------------------
    const float4* wsrc = (const float4*)g_wqkv_t;
    float4 pf[4];
#pragma unroll
    for (int u = 0; u < 4; u++) pf[u] = wsrc[u * 1024 + tid];
    __syncthreads();
#pragma unroll
    for (int u = 0; u < 4; u++) {
        int idx = u * 1024 + tid, r = idx >> 5, c4 = idx & 31;
        *(float4*)(WB + r * S136 + c4 * 4) = pf[u];
    }
    __syncthreads();

    const float scale = 0.17677669529663687f;  // 32^-0.5

    for (int s = 0; s < 3; s++) {
        if (s < 2) {
#pragma unroll
            for (int u = 0; u < 4; u++) pf[u] = wsrc[(s + 1) * 4096 + u * 1024 + tid];
        }
        float acc[2][4];
#pragma unroll
        for (int t = 0; t < 2; t++) acc[t][0] = acc[t][1] = acc[t][2] = acc[t][3] = 0.f;

#pragma unroll 4
        for (int kk = 0; kk < 16; kk++) {
            const int kc = kk * 8;
            float2 aA = *(float2*)(XS + (rb + g)     * S136 + kc + tg2);
            float2 aB = *(float2*)(XS + (rb + g + 8) * S136 + kc + tg2);
#pragma unroll
            for (int t = 0; t < 2; t++) {
                float2 b = *(float2*)(WB + (ngg * 16 + t * 8 + g) * S136 + kc + tg2);
                mma8(acc[t], aA.x, aB.x, aA.y, aB.y, b.x, b.y);
            }
        }
        const int r0 = rb + g, r1 = rb + g + 8;
#pragma unroll
        for (int t = 0; t < 2; t++) {
            const int c0 = ngg * 16 + t * 8 + tg2;
            const float bb0 = qkv_b[s * 128 + c0], bb1 = qkv_b[s * 128 + c0 + 1];
            float v00 = acc[t][0] + bb0, v01 = acc[t][1] + bb1;
            float v10 = acc[t][2] + bb0, v11 = acc[t][3] + bb1;
            if (s == 0) {
                Qb[r0 * S136 + pk(c0)]     = tfs(v00 * scale);
                Qb[r0 * S136 + pk(c0 + 1)] = tfs(v01 * scale);
                Qb[r1 * S136 + pk(c0)]     = tfs(v10 * scale);
                Qb[r1 * S136 + pk(c0 + 1)] = tfs(v11 * scale);
            } else if (s == 1) {
                Kb[r0 * S136 + pk(c0)]     = tfs(v00);
                Kb[r0 * S136 + pk(c0 + 1)] = tfs(v01);
                Kb[r1 * S136 + pk(c0)]     = tfs(v10);
                Kb[r1 * S136 + pk(c0 + 1)] = tfs(v11);
            } else {
                if (r0 < NTOK) {
                    VT[c0 * S72 + pk(r0)]       = tfs(v00);
                    VT[(c0 + 1) * S72 + pk(r0)] = tfs(v01);
                }
                if (r1 < NTOK) {
                    VT[c0 * S72 + pk(r1)]       = tfs(v10);
                    VT[(c0 + 1) * S72 + pk(r1)] = tfs(v11);
                }
            }
        }
        __syncthreads();
        if (s < 2) {
#pragma unroll
            for (int u = 0; u < 4; u++) {
                int idx = u * 1024 + tid, r = idx >> 5, c4 = idx & 31;
                *(float4*)(WB + r * S136 + c4 * 4) = pf[u];
            }
            __syncthreads();
        }
    }

    // ---------------- GEMM2: logits_h[64,64] = Q_h @ K_h^T -----------------
    {
        float acc[4][4];
#pragma unroll
        for (int t = 0; t < 4; t++) acc[t][0] = acc[t][1] = acc[t][2] = acc[t][3] = 0.f;
#pragma unroll
        for (int kk = 0; kk < 4; kk++) {
            const int kc = h * 32 + kk * 8;
            float2 aA = *(float2*)(Qb + (rb2 + g)     * S136 + kc + tg2);
            float2 aB = *(float2*)(Qb + (rb2 + g + 8) * S136 + kc + tg2);
#pragma unroll
            for (int t = 0; t < 4; t++) {
                float2 b = *(float2*)(Kb + (ng2 * 32 + t * 8 + g) * S136 + kc + tg2);
                mma8(acc[t], aA.x, aB.x, aA.y, aB.y, b.x, b.y);
            }
        }
#pragma unroll
        for (int t = 0; t < 4; t++) {
            const int c0 = ng2 * 32 + t * 8 + tg2;
            LBh[(rb2 + g)     * S72 + pk(c0)]     = acc[t][0];
            LBh[(rb2 + g)     * S72 + pk(c0 + 1)] = acc[t][1];
            LBh[(rb2 + g + 8) * S72 + pk(c0)]     = acc[t][2];
            LBh[(rb2 + g + 8) * S72 + pk(c0 + 1)] = acc[t][3];
        }
    }
    __syncthreads();

    // ---------------- softmax: 8-lane segments, 4 rows per warp -------------
    {
        const int v   = w % nmask;
        const int seg = lane >> 3, lj = lane & 7;
        const int pkl = ((lj & 3) << 1) | (lj >> 2);   // pk within 8-group
        const float* rmh = g_rm + (size_t)(v * NHEAD + h) * NTOK * NTOK;
#pragma unroll
        for (int base = 0; base < 64; base += 32) {
            const int i  = base + wg * 4 + seg;
            const bool act = (i < NTOK);
            const int ib = act ? i : 0;
            const float* rm = rmh + ib * NTOK;
            float* Lrow = LBh + ib * S72;
            float vv[7], mx = -3.0e38f;
#pragma unroll
            for (int m = 0; m < 7; m++) {
                const int j = lj + 8 * m;
                const bool okj = act && (j < NTOK);
                vv[m] = okj ? (Lrow[8 * m + pkl] + rm[j]) : -3.0e38f;
                mx = fmaxf(mx, vv[m]);
            }
            mx = fmaxf(mx, __shfl_xor_sync(0xffffffffu, mx, 4));
            mx = fmaxf(mx, __shfl_xor_sync(0xffffffffu, mx, 2));
            mx = fmaxf(mx, __shfl_xor_sync(0xffffffffu, mx, 1));
            float e[7], ssum = 0.f;
#pragma unroll
            for (int m = 0; m < 7; m++) {
                const int j = lj + 8 * m;
                e[m] = (act && j < NTOK) ? __expf(vv[m] - mx) : 0.f;
                ssum += e[m];
            }
            ssum += __shfl_xor_sync(0xffffffffu, ssum, 4);
            ssum += __shfl_xor_sync(0xffffffffu, ssum, 2);
            ssum += __shfl_xor_sync(0xffffffffu, ssum, 1);
            const float inv = 1.0f / ssum;
#pragma unroll
            for (int m = 0; m < 7; m++) {
                const int j = lj + 8 * m;
                if (act && j < NTOK) Lrow[8 * m + pkl] = tfs(e[m] * inv);
            }
        }
    }
    __syncthreads();

    // ---------------- GEMM3: ao_h[64,32] = P_h @ V_h ------------------------
    {
        float acc[2][4];
#pragma unroll
        for (int t = 0; t < 2; t++) acc[t][0] = acc[t][1] = acc[t][2] = acc[t][3] = 0.f;
#pragma unroll
        for (int kk = 0; kk < 8; kk++) {
            const int kc = kk * 8;
            float2 aA = *(float2*)(LBh + (rb2 + g)     * S72 + kc + tg2);
            float2 aB = *(float2*)(LBh + (rb2 + g + 8) * S72 + kc + tg2);
#pragma unroll
            for (int t = 0; t < 2; t++) {
                float2 b = *(float2*)(VT + (h * 32 + ng2 * 16 + t * 8 + g) * S72 + kc + tg2);
                mma8(acc[t], aA.x, aB.x, aA.y, aB.y, b.x, b.y);
            }
        }
#pragma unroll
        for (int t = 0; t < 2; t++) {
            const int c0 = h * 32 + ng2 * 16 + t * 8 + tg2;
            XS[(rb2 + g)     * S136 + pk(c0)]     = tfs(acc[t][0]);
            XS[(rb2 + g)     * S136 + pk(c0 + 1)] = tfs(acc[t][1]);
            XS[(rb2 + g + 8) * S136 + pk(c0)]     = tfs(acc[t][2]);
            XS[(rb2 + g + 8) * S136 + pk(c0 + 1)] = tfs(acc[t][3]);
        }
    }
    // prefetch proj weights (WB/LB still owned by GEMM3 readers until barrier)
    {
        const float4* psrc = (const float4*)g_wproj_t;
#pragma unroll
        for (int u = 0; u < 4; u++) pf[u] = psrc[u * 1024 + tid];
    }
    __syncthreads();
#pragma unroll
    for (int u = 0; u < 4; u++) {
        int idx = u * 1024 + tid, r = idx >> 5, c4 = idx & 31;
        *(float4*)(WB + r * S136 + c4 * 4) = pf[u];
    }
    __syncthreads();

    // ---------------- GEMM4: y[64,128] = ao @ proj_w + b -------------------
    {
        float acc[2][4];
#pragma unroll
        for (int t = 0; t < 2; t++) acc[t][0] = acc[t][1] = acc[t][2] = acc[t][3] = 0.f;
#pragma unroll 4
        for (int kk = 0; kk < 16; kk++) {
            const int kc = kk * 8;
            float2 aA = *(float2*)(XS + (rb + g)     * S136 + kc + tg2);
            float2 aB = *(float2*)(XS + (rb + g + 8) * S136 + kc + tg2);
#pragma unroll
            for (int t = 0; t < 2; t++) {
                float2 b = *(float2*)(WB + (ngg * 16 + t * 8 + g) * S136 + kc + tg2);
                mma8(acc[t], aA.x, aB.x, aA.y, aB.y, b.x, b.y);
            }
        }
        float* Y = Kb;
#pragma unroll
        for (int t = 0; t < 2; t++) {
            const int c0 = ngg * 16 + t * 8 + tg2;
            const float b0 = proj_b[c0], b1 = proj_b[c0 + 1];
            Y[(rb + g)     * S132 + c0]     = acc[t][0] + b0;
            Y[(rb + g)     * S132 + c0 + 1] = acc[t][1] + b1;
            Y[(rb + g + 8) * S132 + c0]     = acc[t][2] + b0;
            Y[(rb + g + 8) * S132 + c0 + 1] = acc[t][3] + b1;
        }
    }
    __syncthreads();

    // ---------------- store --------------------------------------------------
    {
        const float* Y = Kb;
        float4* og = (float4*)(out + (size_t)w * NTOK * CDIM);
        for (int idx = tid; idx < NTOK * 32; idx += 1024) {
            int r = idx >> 5, c4 = idx & 31;
            const float* p = Y + r * S132 + c4 * 4;
            og[r * 32 + c4] = make_float4(p[0], p[1], p[2], p[3]);
        }
    }
}

extern "C" void kernel_launch(void* const* d_in, const int* in_sizes, int n_in,
                              void* d_out, int out_size) {
    const float* x      = (const float*)d_in[0];
    const float* qkv_w  = (const float*)d_in[1];
    const float* qkv_b  = (const float*)d_in[2];
    const float* proj_w = (const float*)d_in[3];
    const float* proj_b = (const float*)d_in[4];
    const float* bias_t = (const float*)d_in[5];
    const float* mask   = (const float*)d_in[6];
    float* out = (float*)d_out;

    const int bw    = in_sizes[0] / (NTOK * CDIM);   // 4096
    const int nmask = in_sizes[6] / (NTOK * NTOK);   // 64

    prepack_w<<<(TC3 * CDIM + CDIM * CDIM + 255) / 256, 256>>>(qkv_w, proj_w);
    {
        int total = nmask * NHEAD * NTOK * NTOK;
        prepack_rm<<<(total + 255) / 256, 256>>>(mask, bias_t, nmask);
    }

    const size_t smem = SMEMF * sizeof(float);       // 215040 B
    cudaFuncSetAttribute(win_attn_kernel,
                         cudaFuncAttributeMaxDynamicSharedMemorySize, (int)smem);
    win_attn_kernel<<<bw, 1024, smem>>>(x, qkv_b, proj_b, out, nmask);
}